// round 1
// baseline (speedup 1.0000x reference)
#include <cuda_runtime.h>

// Problem constants
#define B_  256
#define A_  128
#define D_  5
#define FA_ 256
#define FB_ 64
#define C_  256
#define F_  (FA_ + FB_)   // 320

__global__ __launch_bounds__(C_) void ngh_kernel(
    const float* __restrict__ atoms,   // [B, A, FA]
    const float* __restrict__ bonds,   // [B, A, D, FB]
    const int*   __restrict__ edges,   // [B, A, D]
    const float* __restrict__ W,       // [D, F, C]
    const float* __restrict__ bias,    // [D, C]
    float*       __restrict__ out)     // [B, A, C]
{
    const int row = blockIdx.x;        // b*A + a
    const int tid = threadIdx.x;       // 0..255

    __shared__ float feat[F_];
    __shared__ int   s_edges[D_];

    if (tid < D_) s_edges[tid] = edges[row * D_ + tid];
    __syncthreads();

    const int e0 = s_edges[0], e1 = s_edges[1], e2 = s_edges[2],
              e3 = s_edges[3], e4 = s_edges[4];
    const int deg = (e0 >= 0) + (e1 >= 0) + (e2 >= 0) + (e3 >= 0) + (e4 >= 0);

    if (deg >= D_) {
        // deg==5 never matches mask 0..4 -> output row is exactly zero.
        // Vectorized zero-fill: 64 threads x float4 = 256 floats.
        if (tid < C_ / 4) {
            float4 z = make_float4(0.f, 0.f, 0.f, 0.f);
            reinterpret_cast<float4*>(out + (size_t)row * C_)[tid] = z;
        }
        return;
    }

    // ---- Build feat[0:320] in shared memory ----
    const int batch = row / A_;
    const float* abase = atoms + (size_t)batch * A_ * FA_;

    {   // summed_atom: self + valid neighbors (one feature per thread)
        const int f = tid;  // FA_ == blockDim.x == 256
        float s = atoms[(size_t)row * FA_ + f];
        if (e0 >= 0) s += abase[(size_t)e0 * FA_ + f];
        if (e1 >= 0) s += abase[(size_t)e1 * FA_ + f];
        if (e2 >= 0) s += abase[(size_t)e2 * FA_ + f];
        if (e3 >= 0) s += abase[(size_t)e3 * FA_ + f];
        if (e4 >= 0) s += abase[(size_t)e4 * FA_ + f];
        feat[f] = s;
    }
    if (tid < FB_) {  // summed_bond: sum over all D slots (unconditional, per reference)
        const float* bb = bonds + (size_t)row * D_ * FB_ + tid;
        feat[FA_ + tid] = bb[0] + bb[FB_] + bb[2 * FB_] + bb[3 * FB_] + bb[4 * FB_];
    }
    __syncthreads();

    // ---- GEMV: out[c] = relu(bias[deg,c] + sum_f feat[f] * W[deg,f,c]) ----
    const float* Wd = W + (size_t)deg * F_ * C_ + tid;  // column c = tid, coalesced
    float acc = bias[deg * C_ + tid];
    #pragma unroll 8
    for (int f = 0; f < F_; ++f) {
        acc = fmaf(feat[f], Wd[(size_t)f * C_], acc);
    }
    out[(size_t)row * C_ + tid] = fmaxf(acc, 0.f);
}

extern "C" void kernel_launch(void* const* d_in, const int* in_sizes, int n_in,
                              void* d_out, int out_size)
{
    const float* atoms = (const float*)d_in[0];
    const float* bonds = (const float*)d_in[1];
    const int*   edges = (const int*)  d_in[2];
    const float* W     = (const float*)d_in[3];
    const float* bias  = (const float*)d_in[4];
    float* out = (float*)d_out;

    ngh_kernel<<<B_ * A_, C_>>>(atoms, bonds, edges, W, bias, out);
}